// round 2
// baseline (speedup 1.0000x reference)
#include <cuda_runtime.h>

// Problem constants
#define BB   256
#define CIN  2048
#define LL   150
#define CC   256
#define HH1  8192
#define OUTN 2048

// Tiling
#define BM 64
#define BN 64
#define BK 16
#define PAD 4

// Scratch (static device arrays — no allocation allowed)
__device__ float g_pv [(long)BB * CC * LL];
__device__ float g_q  [(long)BB * CC * LL];
__device__ float g_k  [(long)BB * CC * LL];
__device__ float g_att[(long)BB * LL * LL];
__device__ float g_ao [(long)BB * CC * LL];
__device__ float g_h  [(long)BB * HH1];

// Generic strided batched GEMM:
//   C[b,m,n] = gamma * sum_k A[b,m,k]*B[b,n,k] + bias(+resid)
// bias_mode: 0 none, 1 bias[m], 2 bias[n]
__global__ __launch_bounds__(256) void gemm_kernel(
    const float* __restrict__ A, const float* __restrict__ B,
    const float* __restrict__ bias, int bias_mode,
    const float* __restrict__ gamma, const float* __restrict__ resid,
    float* __restrict__ C,
    int M, int N, int K,
    long sAb, long sAm, long sAk,
    long sBb, long sBn, long sBk,
    long sCb, long sCm, long sCn)
{
    __shared__ float As[BK][BM + PAD];
    __shared__ float Bs[BK][BN + PAD];

    const int b  = blockIdx.z;
    const int m0 = blockIdx.y * BM;
    const int n0 = blockIdx.x * BN;
    const float* Ab = A + (long)b * sAb;
    const float* Bb = B + (long)b * sBb;

    const int tid = threadIdx.x;           // 0..255
    const int tm  = tid >> 4;              // 0..15
    const int tn  = tid & 15;              // 0..15

    float acc[4][4];
#pragma unroll
    for (int i = 0; i < 4; i++)
#pragma unroll
        for (int j = 0; j < 4; j++) acc[i][j] = 0.f;

    const bool a_kfast = (sAk == 1);
    const bool b_nfast = (sBn == 1);

    for (int k0 = 0; k0 < K; k0 += BK) {
        // Load A tile (64 x 16), coalesced mapping chosen by stride
#pragma unroll
        for (int i = 0; i < 4; i++) {
            int idx = tid + i * 256;
            int mm, kk;
            if (a_kfast) { kk = idx & (BK - 1); mm = idx >> 4; }
            else         { mm = idx & (BM - 1); kk = idx >> 6; }
            int m = m0 + mm, k = k0 + kk;
            float v = 0.f;
            if (m < M && k < K) v = Ab[(long)m * sAm + (long)k * sAk];
            As[kk][mm] = v;
        }
        // Load B tile (64 x 16)
#pragma unroll
        for (int i = 0; i < 4; i++) {
            int idx = tid + i * 256;
            int nn, kk;
            if (b_nfast) { nn = idx & (BN - 1); kk = idx >> 6; }
            else         { kk = idx & (BK - 1); nn = idx >> 4; }
            int n = n0 + nn, k = k0 + kk;
            float v = 0.f;
            if (n < N && k < K) v = Bb[(long)n * sBn + (long)k * sBk];
            Bs[kk][nn] = v;
        }
        __syncthreads();

#pragma unroll
        for (int kk = 0; kk < BK; kk++) {
            float4 a4 = *reinterpret_cast<const float4*>(&As[kk][tm * 4]);
            float4 b4 = *reinterpret_cast<const float4*>(&Bs[kk][tn * 4]);
            float ra[4] = {a4.x, a4.y, a4.z, a4.w};
            float rb[4] = {b4.x, b4.y, b4.z, b4.w};
#pragma unroll
            for (int i = 0; i < 4; i++)
#pragma unroll
                for (int j = 0; j < 4; j++)
                    acc[i][j] = fmaf(ra[i], rb[j], acc[i][j]);
        }
        __syncthreads();
    }

    float g = 1.f;
    if (gamma) g = gamma[0];

#pragma unroll
    for (int i = 0; i < 4; i++) {
        int m = m0 + tm * 4 + i;
        if (m >= M) continue;
#pragma unroll
        for (int j = 0; j < 4; j++) {
            int n = n0 + tn * 4 + j;
            if (n >= N) continue;
            float v = acc[i][j] * g;
            if (bias_mode == 1)      v += bias[m];
            else if (bias_mode == 2) v += bias[n];
            long off = (long)b * sCb + (long)m * sCm + (long)n * sCn;
            if (resid) v += resid[off];
            C[off] = v;
        }
    }
}

// In-place row softmax: one block per row of length Lrow
__global__ __launch_bounds__(128) void softmax_kernel(float* __restrict__ att, int Lrow)
{
    __shared__ float red[32];
    const long row = blockIdx.x;
    float* p = att + row * Lrow;
    const int tid = threadIdx.x;

    float m = -1e30f;
    for (int j = tid; j < Lrow; j += blockDim.x) m = fmaxf(m, p[j]);
#pragma unroll
    for (int o = 16; o > 0; o >>= 1) m = fmaxf(m, __shfl_xor_sync(0xffffffffu, m, o));
    if ((tid & 31) == 0) red[tid >> 5] = m;
    __syncthreads();
    if (tid < 32) {
        float v = (tid < (int)((blockDim.x + 31) >> 5)) ? red[tid] : -1e30f;
#pragma unroll
        for (int o = 16; o > 0; o >>= 1) v = fmaxf(v, __shfl_xor_sync(0xffffffffu, v, o));
        red[tid] = v;
    }
    __syncthreads();
    m = red[0];

    float s = 0.f;
    for (int j = tid; j < Lrow; j += blockDim.x) {
        float e = __expf(p[j] - m);
        p[j] = e;
        s += e;
    }
#pragma unroll
    for (int o = 16; o > 0; o >>= 1) s += __shfl_xor_sync(0xffffffffu, s, o);
    __syncthreads();                  // everyone has read red[0] before reuse
    if ((tid & 31) == 0) red[tid >> 5] = s;
    __syncthreads();
    if (tid < 32) {
        float v = (tid < (int)((blockDim.x + 31) >> 5)) ? red[tid] : 0.f;
#pragma unroll
        for (int o = 16; o > 0; o >>= 1) v += __shfl_xor_sync(0xffffffffu, v, o);
        red[tid] = v;
    }
    __syncthreads();
    float inv = 1.f / red[0];
    for (int j = tid; j < Lrow; j += blockDim.x) p[j] *= inv;
}

extern "C" void kernel_launch(void* const* d_in, const int* in_sizes, int n_in,
                              void* d_out, int out_size)
{
    const float* x     = (const float*)d_in[0];
    const float* Wv    = (const float*)d_in[1];
    const float* bv    = (const float*)d_in[2];
    const float* Wq    = (const float*)d_in[3];
    const float* bq    = (const float*)d_in[4];
    const float* Wk    = (const float*)d_in[5];
    const float* bk    = (const float*)d_in[6];
    const float* gamma = (const float*)d_in[7];
    const float* W1    = (const float*)d_in[8];
    const float* b1    = (const float*)d_in[9];
    const float* W2    = (const float*)d_in[10];
    const float* b2    = (const float*)d_in[11];
    float* out = (float*)d_out;

    float *pv, *q, *k, *att, *ao, *h;
    cudaGetSymbolAddress((void**)&pv,  g_pv);
    cudaGetSymbolAddress((void**)&q,   g_q);
    cudaGetSymbolAddress((void**)&k,   g_k);
    cudaGetSymbolAddress((void**)&att, g_att);
    cudaGetSymbolAddress((void**)&ao,  g_ao);
    cudaGetSymbolAddress((void**)&h,   g_h);

    dim3 blk(256);
    const long CL = (long)CC * LL;          // 38400

    // pv[b,o,l] = sum_c Wv[o,c] x[b,c,l] + bv[o]
    gemm_kernel<<<dim3((LL + BN - 1) / BN, (CC + BM - 1) / BM, BB), blk>>>(
        Wv, x, bv, 1, nullptr, nullptr, pv,
        CC, LL, CIN,
        0L, (long)CIN, 1L,
        (long)CIN * LL, 1L, (long)LL,
        CL, (long)LL, 1L);

    // q = Wq pv + bq
    gemm_kernel<<<dim3((LL + BN - 1) / BN, (CC + BM - 1) / BM, BB), blk>>>(
        Wq, pv, bq, 1, nullptr, nullptr, q,
        CC, LL, CC,
        0L, (long)CC, 1L,
        CL, 1L, (long)LL,
        CL, (long)LL, 1L);

    // k = Wk pv + bk
    gemm_kernel<<<dim3((LL + BN - 1) / BN, (CC + BM - 1) / BM, BB), blk>>>(
        Wk, pv, bk, 1, nullptr, nullptr, k,
        CC, LL, CC,
        0L, (long)CC, 1L,
        CL, 1L, (long)LL,
        CL, (long)LL, 1L);

    // energy[b,i,j] = sum_c q[b,c,i] k[b,c,j]
    gemm_kernel<<<dim3((LL + BN - 1) / BN, (LL + BM - 1) / BM, BB), blk>>>(
        q, k, nullptr, 0, nullptr, nullptr, att,
        LL, LL, CC,
        CL, 1L, (long)LL,
        CL, 1L, (long)LL,
        (long)LL * LL, (long)LL, 1L);

    // softmax over last dim, in place
    softmax_kernel<<<BB * LL, 128>>>(att, LL);

    // ao[b,c,l] = gamma * sum_m pv[b,c,m] att[b,l,m] + pv[b,c,l]
    gemm_kernel<<<dim3((LL + BN - 1) / BN, (CC + BM - 1) / BM, BB), blk>>>(
        pv, att, nullptr, 0, gamma, pv, ao,
        CC, LL, LL,
        CL, (long)LL, 1L,
        (long)LL * LL, (long)LL, 1L,
        CL, (long)LL, 1L);

    // h[b,j] = sum_k ao_flat[b,k] W1[j,k] + b1[j]   (M=B, N=H1, K=C*L)
    gemm_kernel<<<dim3(HH1 / BN, BB / BM, 1), blk>>>(
        ao, W1, b1, 2, nullptr, nullptr, h,
        BB, HH1, (int)CL,
        0L, CL, 1L,
        0L, CL, 1L,
        0L, (long)HH1, 1L);

    // out[b,j] = sum_k h[b,k] W2[j,k] + b2[j]   (M=B, N=OUT, K=H1)
    gemm_kernel<<<dim3(OUTN / BN, BB / BM, 1), blk>>>(
        h, W2, b2, 2, nullptr, nullptr, out,
        BB, OUTN, HH1,
        0L, (long)HH1, 1L,
        0L, (long)HH1, 1L,
        0L, (long)OUTN, 1L);
}

// round 4
// speedup vs baseline: 1.9789x; 1.9789x over previous
#include <cuda_runtime.h>

// Problem constants
#define BB   256
#define CIN  2048
#define LL   150
#define CC   256
#define HH1  8192
#define OUTN 2048

// Tiling
#define BM 128
#define BN 128
#define BK 16
#define SST 136   // smem row stride (BM+8): bank-conflict-free fragment loads

// Scratch (static device arrays — no allocation allowed)
__device__ float g_pv [(long)BB * CC * LL];
__device__ float g_q  [(long)BB * CC * LL];
__device__ float g_k  [(long)BB * CC * LL];
__device__ float g_att[(long)BB * LL * LL];
__device__ float g_ao [(long)BB * CC * LL];
__device__ float g_h  [(long)BB * HH1];

__device__ __forceinline__ unsigned f2tf32(float f) {
    unsigned u;
    asm("cvt.rna.tf32.f32 %0, %1;" : "=r"(u) : "f"(f));
    return u;
}

// Generic strided batched GEMM on tensor cores (tf32 mma.sync):
//   C[b,m,n] = gamma * sum_k A[b,m,k]*B[b,n,k] + bias(+resid)
// bias_mode: 0 none, 1 bias[m], 2 bias[n]
__global__ __launch_bounds__(256) void gemm_tc(
    const float* __restrict__ A, const float* __restrict__ B,
    const float* __restrict__ bias, int bias_mode,
    const float* __restrict__ gamma, const float* __restrict__ resid,
    float* __restrict__ C,
    int M, int N, int K,
    long sAb, long sAm, long sAk,
    long sBb, long sBn, long sBk,
    long sCb, long sCm, long sCn)
{
    __shared__ unsigned As[2][BK][SST];
    __shared__ unsigned Bs[2][BK][SST];

    const int b  = blockIdx.z;
    const int m0 = blockIdx.y * BM;
    const int n0 = blockIdx.x * BN;
    const float* Ab = A + (long)b * sAb;
    const float* Bb = B + (long)b * sBb;

    const int tid  = threadIdx.x;
    const int warp = tid >> 5;
    const int lane = tid & 31;
    const int wm0  = (warp >> 2) * 64;   // warp m-origin within block tile
    const int wn0  = (warp & 3) * 32;    // warp n-origin
    const int lr   = lane >> 2;          // 0..7
    const int lc   = lane & 3;           // 0..3

    const bool a_kfast = (sAk == 1);
    const bool b_nfast = (sBn == 1);

    float acc[4][4][4];
#pragma unroll
    for (int mi = 0; mi < 4; mi++)
#pragma unroll
        for (int ni = 0; ni < 4; ni++)
#pragma unroll
            for (int e = 0; e < 4; e++) acc[mi][ni][e] = 0.f;

    const int T = (K + BK - 1) / BK;

    // ---- load tile helpers (inlined loops; 8 elems per thread per operand) ----
    unsigned ra[8], rb[8];

#define LOAD_TILE(k0)                                                          \
    {                                                                          \
        _Pragma("unroll")                                                      \
        for (int i = 0; i < 8; i++) {                                          \
            int idx = tid + i * 256;                                           \
            int mm, kk;                                                        \
            if (a_kfast) { kk = idx & (BK - 1); mm = idx >> 4; }               \
            else         { mm = idx & (BM - 1); kk = idx >> 7; }               \
            int m = m0 + mm, k = (k0) + kk;                                    \
            float v = 0.f;                                                     \
            if (m < M && k < K) v = Ab[(long)m * sAm + (long)k * sAk];         \
            ra[i] = f2tf32(v);                                                 \
        }                                                                      \
        _Pragma("unroll")                                                      \
        for (int i = 0; i < 8; i++) {                                          \
            int idx = tid + i * 256;                                           \
            int nn, kk;                                                        \
            if (b_nfast) { nn = idx & (BN - 1); kk = idx >> 7; }               \
            else         { kk = idx & (BK - 1); nn = idx >> 4; }               \
            int n = n0 + nn, k = (k0) + kk;                                    \
            float v = 0.f;                                                     \
            if (n < N && k < K) v = Bb[(long)n * sBn + (long)k * sBk];         \
            rb[i] = f2tf32(v);                                                 \
        }                                                                      \
    }

#define STORE_TILE(buf)                                                        \
    {                                                                          \
        _Pragma("unroll")                                                      \
        for (int i = 0; i < 8; i++) {                                          \
            int idx = tid + i * 256;                                           \
            int mm, kk;                                                        \
            if (a_kfast) { kk = idx & (BK - 1); mm = idx >> 4; }               \
            else         { mm = idx & (BM - 1); kk = idx >> 7; }               \
            As[buf][kk][mm] = ra[i];                                           \
        }                                                                      \
        _Pragma("unroll")                                                      \
        for (int i = 0; i < 8; i++) {                                          \
            int idx = tid + i * 256;                                           \
            int nn, kk;                                                        \
            if (b_nfast) { nn = idx & (BN - 1); kk = idx >> 7; }               \
            else         { kk = idx & (BK - 1); nn = idx >> 4; }               \
            Bs[buf][kk][nn] = rb[i];                                           \
        }                                                                      \
    }

    // Prologue: tile 0 -> buffer 0
    LOAD_TILE(0);
    STORE_TILE(0);
    __syncthreads();

    for (int t = 0; t < T; t++) {
        const int cur = t & 1;

        if (t + 1 < T) LOAD_TILE((t + 1) * BK);

        // Compute on buffer `cur`: two k=8 slices
#pragma unroll
        for (int ks = 0; ks < 2; ks++) {
            const int kb = ks * 8;
            unsigned af[4][4], bf[4][2];
#pragma unroll
            for (int mi = 0; mi < 4; mi++) {
                int m = wm0 + mi * 16 + lr;
                af[mi][0] = As[cur][kb + lc    ][m];
                af[mi][1] = As[cur][kb + lc    ][m + 8];
                af[mi][2] = As[cur][kb + lc + 4][m];
                af[mi][3] = As[cur][kb + lc + 4][m + 8];
            }
#pragma unroll
            for (int ni = 0; ni < 4; ni++) {
                int n = wn0 + ni * 8 + lr;
                bf[ni][0] = Bs[cur][kb + lc    ][n];
                bf[ni][1] = Bs[cur][kb + lc + 4][n];
            }
#pragma unroll
            for (int mi = 0; mi < 4; mi++)
#pragma unroll
                for (int ni = 0; ni < 4; ni++) {
                    asm volatile(
                        "mma.sync.aligned.m16n8k8.row.col.f32.tf32.tf32.f32 "
                        "{%0,%1,%2,%3}, {%4,%5,%6,%7}, {%8,%9}, {%0,%1,%2,%3};"
                        : "+f"(acc[mi][ni][0]), "+f"(acc[mi][ni][1]),
                          "+f"(acc[mi][ni][2]), "+f"(acc[mi][ni][3])
                        : "r"(af[mi][0]), "r"(af[mi][1]),
                          "r"(af[mi][2]), "r"(af[mi][3]),
                          "r"(bf[ni][0]), "r"(bf[ni][1]));
                }
        }

        if (t + 1 < T) STORE_TILE(cur ^ 1);
        __syncthreads();
    }

    // Epilogue
    float g = 1.f;
    if (gamma) g = gamma[0];

#pragma unroll
    for (int mi = 0; mi < 4; mi++) {
#pragma unroll
        for (int ni = 0; ni < 4; ni++) {
#pragma unroll
            for (int e = 0; e < 4; e++) {
                int r = m0 + wm0 + mi * 16 + lr + ((e >= 2) ? 8 : 0);
                int c = n0 + wn0 + ni * 8 + 2 * lc + (e & 1);
                if (r < M && c < N) {
                    float v = acc[mi][ni][e] * g;
                    if (bias_mode == 1)      v += bias[r];
                    else if (bias_mode == 2) v += bias[c];
                    long off = (long)b * sCb + (long)r * sCm + (long)c * sCn;
                    if (resid) v += resid[off];
                    C[off] = v;
                }
            }
        }
    }
#undef LOAD_TILE
#undef STORE_TILE
}

// In-place row softmax: one block per row of length Lrow
__global__ __launch_bounds__(128) void softmax_kernel(float* __restrict__ att, int Lrow)
{
    __shared__ float red[32];
    const long row = blockIdx.x;
    float* p = att + row * Lrow;
    const int tid = threadIdx.x;

    float m = -1e30f;
    for (int j = tid; j < Lrow; j += blockDim.x) m = fmaxf(m, p[j]);
#pragma unroll
    for (int o = 16; o > 0; o >>= 1) m = fmaxf(m, __shfl_xor_sync(0xffffffffu, m, o));
    if ((tid & 31) == 0) red[tid >> 5] = m;
    __syncthreads();
    if (tid < 32) {
        float v = (tid < (int)((blockDim.x + 31) >> 5)) ? red[tid] : -1e30f;
#pragma unroll
        for (int o = 16; o > 0; o >>= 1) v = fmaxf(v, __shfl_xor_sync(0xffffffffu, v, o));
        red[tid] = v;
    }
    __syncthreads();
    m = red[0];

    float s = 0.f;
    for (int j = tid; j < Lrow; j += blockDim.x) {
        float e = __expf(p[j] - m);
        p[j] = e;
        s += e;
    }
#pragma unroll
    for (int o = 16; o > 0; o >>= 1) s += __shfl_xor_sync(0xffffffffu, s, o);
    __syncthreads();
    if ((tid & 31) == 0) red[tid >> 5] = s;
    __syncthreads();
    if (tid < 32) {
        float v = (tid < (int)((blockDim.x + 31) >> 5)) ? red[tid] : 0.f;
#pragma unroll
        for (int o = 16; o > 0; o >>= 1) v += __shfl_xor_sync(0xffffffffu, v, o);
        red[tid] = v;
    }
    __syncthreads();
    float inv = 1.f / red[0];
    for (int j = tid; j < Lrow; j += blockDim.x) p[j] *= inv;
}

extern "C" void kernel_launch(void* const* d_in, const int* in_sizes, int n_in,
                              void* d_out, int out_size)
{
    const float* x     = (const float*)d_in[0];
    const float* Wv    = (const float*)d_in[1];
    const float* bv    = (const float*)d_in[2];
    const float* Wq    = (const float*)d_in[3];
    const float* bq    = (const float*)d_in[4];
    const float* Wk    = (const float*)d_in[5];
    const float* bk    = (const float*)d_in[6];
    const float* gamma = (const float*)d_in[7];
    const float* W1    = (const float*)d_in[8];
    const float* b1    = (const float*)d_in[9];
    const float* W2    = (const float*)d_in[10];
    const float* b2    = (const float*)d_in[11];
    float* out = (float*)d_out;

    float *pv, *q, *k, *att, *ao, *h;
    cudaGetSymbolAddress((void**)&pv,  g_pv);
    cudaGetSymbolAddress((void**)&q,   g_q);
    cudaGetSymbolAddress((void**)&k,   g_k);
    cudaGetSymbolAddress((void**)&att, g_att);
    cudaGetSymbolAddress((void**)&ao,  g_ao);
    cudaGetSymbolAddress((void**)&h,   g_h);

    dim3 blk(256);
    const long CL = (long)CC * LL;          // 38400

    // pv[b,o,l] = sum_c Wv[o,c] x[b,c,l] + bv[o]
    gemm_tc<<<dim3((LL + BN - 1) / BN, (CC + BM - 1) / BM, BB), blk>>>(
        Wv, x, bv, 1, nullptr, nullptr, pv,
        CC, LL, CIN,
        0L, (long)CIN, 1L,
        (long)CIN * LL, 1L, (long)LL,
        CL, (long)LL, 1L);

    // q = Wq pv + bq
    gemm_tc<<<dim3((LL + BN - 1) / BN, (CC + BM - 1) / BM, BB), blk>>>(
        Wq, pv, bq, 1, nullptr, nullptr, q,
        CC, LL, CC,
        0L, (long)CC, 1L,
        CL, 1L, (long)LL,
        CL, (long)LL, 1L);

    // k = Wk pv + bk
    gemm_tc<<<dim3((LL + BN - 1) / BN, (CC + BM - 1) / BM, BB), blk>>>(
        Wk, pv, bk, 1, nullptr, nullptr, k,
        CC, LL, CC,
        0L, (long)CC, 1L,
        CL, 1L, (long)LL,
        CL, (long)LL, 1L);

    // energy[b,i,j] = sum_c q[b,c,i] k[b,c,j]
    gemm_tc<<<dim3((LL + BN - 1) / BN, (LL + BM - 1) / BM, BB), blk>>>(
        q, k, nullptr, 0, nullptr, nullptr, att,
        LL, LL, CC,
        CL, 1L, (long)LL,
        CL, 1L, (long)LL,
        (long)LL * LL, (long)LL, 1L);

    // softmax over last dim, in place
    softmax_kernel<<<BB * LL, 128>>>(att, LL);

    // ao[b,c,l] = gamma * sum_m pv[b,c,m] att[b,l,m] + pv[b,c,l]
    gemm_tc<<<dim3((LL + BN - 1) / BN, (CC + BM - 1) / BM, BB), blk>>>(
        pv, att, nullptr, 0, gamma, pv, ao,
        CC, LL, LL,
        CL, (long)LL, 1L,
        (long)LL * LL, (long)LL, 1L,
        CL, (long)LL, 1L);

    // h[b,j] = sum_k ao_flat[b,k] W1[j,k] + b1[j]   (M=B, N=H1, K=C*L)
    gemm_tc<<<dim3(HH1 / BN, BB / BM, 1), blk>>>(
        ao, W1, b1, 2, nullptr, nullptr, h,
        BB, HH1, (int)CL,
        0L, CL, 1L,
        0L, CL, 1L,
        0L, (long)HH1, 1L);

    // out[b,j] = sum_k h[b,k] W2[j,k] + b2[j]   (M=B, N=OUT, K=H1)
    gemm_tc<<<dim3(OUTN / BN, BB / BM, 1), blk>>>(
        h, W2, b2, 2, nullptr, nullptr, out,
        BB, OUTN, HH1,
        0L, (long)HH1, 1L,
        0L, (long)HH1, 1L,
        0L, (long)OUTN, 1L);
}

// round 5
// speedup vs baseline: 4.6215x; 2.3353x over previous
#include <cuda_runtime.h>

// Problem constants
#define BB   256
#define CIN  2048
#define LL   150
#define LP   160          // padded L
#define CC   256
#define HH1  8192
#define OUTN 2048

#define CL160 ((long)CC * LP)        // 40960
#define ATTS  ((long)LP * LP)        // 25600
#define CL150 ((long)CC * LL)        // 38400

// Tiling
#define BMT 128
#define BNT 128
#define BKT 16
#define SKF 20    // smem row stride for KFAST layout  [mn][k]
#define SMF 136   // smem row stride for MNFAST layout [k][mn]

// Scratch (static device arrays — no allocation allowed). +4096 tail pads.
__device__ float g_pv [(long)BB * CL160 + 4096];
__device__ float g_q  [(long)BB * CL160 + 4096];
__device__ float g_k  [(long)BB * CL160 + 4096];
__device__ float g_att[(long)BB * ATTS  + 4096];
__device__ float g_ao [(long)BB * CL150];
__device__ float g_h  [(long)BB * HH1];
__device__ float g_hp [4L * BB * HH1];
__device__ float g_op [8L * BB * OUTN];

__device__ __forceinline__ unsigned f2tf32(float f) {
    unsigned u;
    asm("cvt.rna.tf32.f32 %0, %1;" : "=r"(u) : "f"(f));
    return u;
}

// Load modes: 0 = KFAST (stride-1 along k, vectorized)
//             1 = MNFAST (stride-1 along m/n, vectorized)
//             2 = MNFAST_GUARD (stride-1 along m/n, scalar + invariant predicate)
template<int AM, int BMo>
__global__ __launch_bounds__(256) void gemm2(
    const float* __restrict__ A, const float* __restrict__ B,
    const float* __restrict__ bias, int bias_mode,
    const float* __restrict__ gamma, const float* __restrict__ resid,
    long sRb, long sRm, long sRn,
    float* __restrict__ C,
    int M, int N, int K,
    long sAb, long sAm, long sAk,
    long sBb, long sBn, long sBk,
    long sCb, long sCm, long sCn)
{
    __shared__ unsigned sm[2][2][2560];   // [buf][A/B][layout-dependent]

    const int b  = blockIdx.z;
    const int m0 = blockIdx.y * BMT;
    const int n0 = blockIdx.x * BNT;

    const int tid  = threadIdx.x;
    const int warp = tid >> 5;
    const int lane = tid & 31;
    const int wm0  = (warp >> 2) * 64;
    const int wn0  = (warp & 3) * 32;
    const int lr   = lane >> 2;
    const int lc   = lane & 3;

    // ---- per-thread load setup (all loop-invariant) ----
    const float* Abase = A + (long)b * sAb;
    const float* Bbase = B + (long)b * sBb;
    long aoff[2]; int sa[2];
    long boff[8]; int sb[8]; bool bok[8];
    long aAdv, bAdv;

    if (AM == 0) {  // KFAST: vec, smem [m][SKF]
#pragma unroll
        for (int i = 0; i < 2; i++) {
            int v = tid + i * 256;
            int mm = v >> 2, kv = (v & 3) * 4;
            aoff[i] = (long)(m0 + mm) * sAm + kv;
            sa[i]   = mm * SKF + kv;
        }
        aAdv = BKT;
    } else {        // MNFAST: vec, smem [k][SMF]
#pragma unroll
        for (int i = 0; i < 2; i++) {
            int v = tid + i * 256;
            int kk = v >> 5, mv = (v & 31) * 4;
            aoff[i] = (long)kk * sAk + (m0 + mv);
            sa[i]   = kk * SMF + mv;
        }
        aAdv = BKT * sAk;
    }
    if (BMo == 0) {
#pragma unroll
        for (int i = 0; i < 2; i++) {
            int v = tid + i * 256;
            int nn = v >> 2, kv = (v & 3) * 4;
            boff[i] = (long)(n0 + nn) * sBn + kv;
            sb[i]   = nn * SKF + kv;
        }
        bAdv = BKT;
    } else if (BMo == 1) {
#pragma unroll
        for (int i = 0; i < 2; i++) {
            int v = tid + i * 256;
            int kk = v >> 5, nv = (v & 31) * 4;
            boff[i] = (long)kk * sBk + (n0 + nv);
            sb[i]   = kk * SMF + nv;
        }
        bAdv = BKT * sBk;
    } else {        // GUARD: scalar
#pragma unroll
        for (int j = 0; j < 8; j++) {
            int idx = tid + j * 256;
            int nn = idx & 127, kk = idx >> 7;
            boff[j] = (long)kk * sBk + (n0 + nn);
            sb[j]   = kk * SMF + nn;
            bok[j]  = (n0 + nn) < N;
        }
        bAdv = BKT * sBk;
    }

    float acc[4][4][4];
#pragma unroll
    for (int mi = 0; mi < 4; mi++)
#pragma unroll
        for (int ni = 0; ni < 4; ni++)
#pragma unroll
            for (int e = 0; e < 4; e++) acc[mi][ni][e] = 0.f;

    const int T = K / BKT;   // all K are multiples of 16

    float4 la[2], lbv[2];
    float  lbs[8];

#define LOAD_G()                                                               \
    {                                                                          \
        la[0] = *(const float4*)(Abase + aoff[0]);                             \
        la[1] = *(const float4*)(Abase + aoff[1]);                             \
        if (BMo == 2) {                                                        \
            _Pragma("unroll")                                                  \
            for (int j = 0; j < 8; j++)                                        \
                lbs[j] = bok[j] ? Bbase[boff[j]] : 0.f;                        \
        } else {                                                               \
            lbv[0] = *(const float4*)(Bbase + boff[0]);                        \
            lbv[1] = *(const float4*)(Bbase + boff[1]);                        \
        }                                                                      \
        Abase += aAdv; Bbase += bAdv;                                          \
    }

#define STORE_S(buf)                                                           \
    {                                                                          \
        unsigned* sA = sm[buf][0];                                             \
        unsigned* sB = sm[buf][1];                                             \
        _Pragma("unroll")                                                      \
        for (int i = 0; i < 2; i++) {                                          \
            float* f = (float*)&la[i];                                         \
            if (AM == 0) {                                                     \
                uint4 u = {f2tf32(f[0]), f2tf32(f[1]), f2tf32(f[2]), f2tf32(f[3])}; \
                *(uint4*)(sA + sa[i]) = u;                                     \
            } else {                                                           \
                uint4 u = {f2tf32(f[0]), f2tf32(f[1]), f2tf32(f[2]), f2tf32(f[3])}; \
                *(uint4*)(sA + sa[i]) = u;                                     \
            }                                                                  \
        }                                                                      \
        if (BMo == 2) {                                                        \
            _Pragma("unroll")                                                  \
            for (int j = 0; j < 8; j++) sB[sb[j]] = f2tf32(lbs[j]);            \
        } else {                                                               \
            _Pragma("unroll")                                                  \
            for (int i = 0; i < 2; i++) {                                      \
                float* f = (float*)&lbv[i];                                    \
                uint4 u = {f2tf32(f[0]), f2tf32(f[1]), f2tf32(f[2]), f2tf32(f[3])}; \
                *(uint4*)(sB + sb[i]) = u;                                     \
            }                                                                  \
        }                                                                      \
    }

    LOAD_G();
    STORE_S(0);
    __syncthreads();

    for (int t = 0; t < T; t++) {
        const int cur = t & 1;
        if (t + 1 < T) LOAD_G();

        const unsigned* sA = sm[cur][0];
        const unsigned* sB = sm[cur][1];
#pragma unroll
        for (int ks = 0; ks < 2; ks++) {
            const int kb = ks * 8;
            unsigned af[4][4], bf[4][2];
#pragma unroll
            for (int mi = 0; mi < 4; mi++) {
                int m = wm0 + mi * 16 + lr;
                if (AM == 0) {
                    af[mi][0] = sA[m * SKF + kb + lc];
                    af[mi][1] = sA[(m + 8) * SKF + kb + lc];
                    af[mi][2] = sA[m * SKF + kb + lc + 4];
                    af[mi][3] = sA[(m + 8) * SKF + kb + lc + 4];
                } else {
                    af[mi][0] = sA[(kb + lc) * SMF + m];
                    af[mi][1] = sA[(kb + lc) * SMF + m + 8];
                    af[mi][2] = sA[(kb + lc + 4) * SMF + m];
                    af[mi][3] = sA[(kb + lc + 4) * SMF + m + 8];
                }
            }
#pragma unroll
            for (int ni = 0; ni < 4; ni++) {
                int n = wn0 + ni * 8 + lr;
                if (BMo == 0) {
                    bf[ni][0] = sB[n * SKF + kb + lc];
                    bf[ni][1] = sB[n * SKF + kb + lc + 4];
                } else {
                    bf[ni][0] = sB[(kb + lc) * SMF + n];
                    bf[ni][1] = sB[(kb + lc + 4) * SMF + n];
                }
            }
#pragma unroll
            for (int mi = 0; mi < 4; mi++)
#pragma unroll
                for (int ni = 0; ni < 4; ni++) {
                    asm volatile(
                        "mma.sync.aligned.m16n8k8.row.col.f32.tf32.tf32.f32 "
                        "{%0,%1,%2,%3}, {%4,%5,%6,%7}, {%8,%9}, {%0,%1,%2,%3};"
                        : "+f"(acc[mi][ni][0]), "+f"(acc[mi][ni][1]),
                          "+f"(acc[mi][ni][2]), "+f"(acc[mi][ni][3])
                        : "r"(af[mi][0]), "r"(af[mi][1]),
                          "r"(af[mi][2]), "r"(af[mi][3]),
                          "r"(bf[ni][0]), "r"(bf[ni][1]));
                }
        }
        if (t + 1 < T) STORE_S(cur ^ 1);
        __syncthreads();
    }

    float g = 1.f;
    if (gamma) g = gamma[0];
    const bool has_resid = (resid != nullptr);

#pragma unroll
    for (int mi = 0; mi < 4; mi++) {
#pragma unroll
        for (int ni = 0; ni < 4; ni++) {
#pragma unroll
            for (int e = 0; e < 4; e++) {
                int r = m0 + wm0 + mi * 16 + lr + ((e >= 2) ? 8 : 0);
                int c = n0 + wn0 + ni * 8 + 2 * lc + (e & 1);
                if (r < M && c < N) {
                    float v = acc[mi][ni][e] * g;
                    if (bias_mode == 1)      v += bias[r];
                    else if (bias_mode == 2) v += bias[c];
                    if (has_resid) v += resid[(long)b * sRb + (long)r * sRm + (long)c * sRn];
                    C[(long)b * sCb + (long)r * sCm + (long)c * sCn] = v;
                }
            }
        }
    }
#undef LOAD_G
#undef STORE_S
}

// Row softmax on padded att: row length 150, stride 160, pads untouched (zero)
__global__ __launch_bounds__(128) void softmax_kernel(float* __restrict__ att)
{
    __shared__ float red[32];
    const int bi = blockIdx.x / LL;
    const int li = blockIdx.x % LL;
    float* p = att + (long)bi * ATTS + (long)li * LP;
    const int tid = threadIdx.x;

    float m = -1e30f;
    for (int j = tid; j < LL; j += 128) m = fmaxf(m, p[j]);
#pragma unroll
    for (int o = 16; o > 0; o >>= 1) m = fmaxf(m, __shfl_xor_sync(0xffffffffu, m, o));
    if ((tid & 31) == 0) red[tid >> 5] = m;
    __syncthreads();
    if (tid < 32) {
        float v = (tid < 4) ? red[tid] : -1e30f;
#pragma unroll
        for (int o = 16; o > 0; o >>= 1) v = fmaxf(v, __shfl_xor_sync(0xffffffffu, v, o));
        red[tid] = v;
    }
    __syncthreads();
    m = red[0];

    float s = 0.f;
    for (int j = tid; j < LL; j += 128) {
        float e = __expf(p[j] - m);
        p[j] = e;
        s += e;
    }
#pragma unroll
    for (int o = 16; o > 0; o >>= 1) s += __shfl_xor_sync(0xffffffffu, s, o);
    __syncthreads();
    if ((tid & 31) == 0) red[tid >> 5] = s;
    __syncthreads();
    if (tid < 32) {
        float v = (tid < 4) ? red[tid] : 0.f;
#pragma unroll
        for (int o = 16; o > 0; o >>= 1) v += __shfl_xor_sync(0xffffffffu, v, o);
        red[tid] = v;
    }
    __syncthreads();
    float inv = 1.f / red[0];
    for (int j = tid; j < LL; j += 128) p[j] *= inv;
}

// h = sum_z hp + b1
__global__ __launch_bounds__(256) void reduce_fc1(
    const float* __restrict__ hp, const float* __restrict__ b1, float* __restrict__ h)
{
    long i = (long)blockIdx.x * 256 + threadIdx.x;
    const long S = (long)BB * HH1;
    float v = b1[i & (HH1 - 1)];
#pragma unroll
    for (int z = 0; z < 4; z++) v += hp[i + z * S];
    h[i] = v;
}

// out = sum_z op + b2
__global__ __launch_bounds__(256) void reduce_fc2(
    const float* __restrict__ op, const float* __restrict__ b2, float* __restrict__ out)
{
    long i = (long)blockIdx.x * 256 + threadIdx.x;
    const long S = (long)BB * OUTN;
    float v = b2[i & (OUTN - 1)];
#pragma unroll
    for (int z = 0; z < 8; z++) v += op[i + z * S];
    out[i] = v;
}

extern "C" void kernel_launch(void* const* d_in, const int* in_sizes, int n_in,
                              void* d_out, int out_size)
{
    const float* x     = (const float*)d_in[0];
    const float* Wv    = (const float*)d_in[1];
    const float* bv    = (const float*)d_in[2];
    const float* Wq    = (const float*)d_in[3];
    const float* bq    = (const float*)d_in[4];
    const float* Wk    = (const float*)d_in[5];
    const float* bk    = (const float*)d_in[6];
    const float* gamma = (const float*)d_in[7];
    const float* W1    = (const float*)d_in[8];
    const float* b1    = (const float*)d_in[9];
    const float* W2    = (const float*)d_in[10];
    const float* b2    = (const float*)d_in[11];
    float* out = (float*)d_out;

    float *pv, *q, *k, *att, *ao, *h, *hp, *op;
    cudaGetSymbolAddress((void**)&pv,  g_pv);
    cudaGetSymbolAddress((void**)&q,   g_q);
    cudaGetSymbolAddress((void**)&k,   g_k);
    cudaGetSymbolAddress((void**)&att, g_att);
    cudaGetSymbolAddress((void**)&ao,  g_ao);
    cudaGetSymbolAddress((void**)&h,   g_h);
    cudaGetSymbolAddress((void**)&hp,  g_hp);
    cudaGetSymbolAddress((void**)&op,  g_op);

    dim3 blk(256);

    // Zero pads (pv K-dim pads and att K-dim pads must be 0; memset whole arrays)
    cudaMemsetAsync(pv,  0, ((long)BB * CL160 + 4096) * sizeof(float));
    cudaMemsetAsync(att, 0, ((long)BB * ATTS  + 4096) * sizeof(float));

    // pv[b,o,l] = Wv x + bv     A=Wv (KFAST), B=x (GUARD, real L=150)
    gemm2<0, 2><<<dim3(2, 2, BB), blk>>>(
        Wv, x, bv, 1, nullptr, nullptr, 0, 0, 0, pv,
        CC, LL, CIN,
        0L, (long)CIN, 1L,
        (long)CIN * LL, 1L, (long)LL,
        CL160, (long)LP, 1L);

    // q = Wq pv + bq            A=Wq (KFAST), B=pv (MNFAST, padded)
    gemm2<0, 1><<<dim3(2, 2, BB), blk>>>(
        Wq, pv, bq, 1, nullptr, nullptr, 0, 0, 0, q,
        CC, LL, CC,
        0L, (long)CC, 1L,
        CL160, 1L, (long)LP,
        CL160, (long)LP, 1L);

    // k = Wk pv + bk
    gemm2<0, 1><<<dim3(2, 2, BB), blk>>>(
        Wk, pv, bk, 1, nullptr, nullptr, 0, 0, 0, k,
        CC, LL, CC,
        0L, (long)CC, 1L,
        CL160, 1L, (long)LP,
        CL160, (long)LP, 1L);

    // energy[b,i,j] = sum_c q[b,c,i] k[b,c,j]   A=q (MNFAST), B=k (MNFAST)
    gemm2<1, 1><<<dim3(2, 2, BB), blk>>>(
        q, k, nullptr, 0, nullptr, nullptr, 0, 0, 0, att,
        LL, LL, CC,
        CL160, 1L, (long)LP,
        CL160, 1L, (long)LP,
        ATTS, (long)LP, 1L);

    softmax_kernel<<<BB * LL, 128>>>(att);

    // ao[b,c,l] = gamma * sum_m pv[b,c,m] att[b,l,m] + pv ; compact output
    gemm2<0, 0><<<dim3(2, 2, BB), blk>>>(
        pv, att, nullptr, 0, gamma, pv, CL160, (long)LP, 1L, ao,
        CC, LL, LP,
        CL160, (long)LP, 1L,
        ATTS, (long)LP, 1L,
        CL150, (long)LL, 1L);

    // fc1 split-K=4: hp[z] = ao @ W1^T (chunk 9600)
    gemm2<0, 0><<<dim3(HH1 / BNT, BB / BMT, 4), blk>>>(
        ao, W1, nullptr, 0, nullptr, nullptr, 0, 0, 0, hp,
        BB, HH1, 9600,
        9600L, CL150, 1L,
        9600L, CL150, 1L,
        (long)BB * HH1, (long)HH1, 1L);

    reduce_fc1<<<(BB * HH1) / 256, 256>>>(hp, b1, h);

    // fc2 split-K=8: op[z] = h @ W2^T (chunk 1024)
    gemm2<0, 0><<<dim3(OUTN / BNT, BB / BMT, 8), blk>>>(
        h, W2, nullptr, 0, nullptr, nullptr, 0, 0, 0, op,
        BB, OUTN, 1024,
        1024L, (long)HH1, 1L,
        1024L, (long)HH1, 1L,
        (long)BB * OUTN, (long)OUTN, 1L);

    reduce_fc2<<<(BB * OUTN) / 256, 256>>>(op, b2, out);
}